// round 17
// baseline (speedup 1.0000x reference)
#include <cuda_runtime.h>
#include <cuda_fp16.h>
#include <stdint.h>

#define CHN   128
#define HWSZ  65536
#define BATCH 4
#define BCHW  33554432ll
#define NWIN  4096
#define TOK   64

__device__ __align__(128) __half g_wh[229376];
__device__ __align__(128) __half g_qkT[4ll * BCHW];
__device__ __align__(128) __half g_vwin[2ll * BCHW];
__device__ __align__(128) __half g_attn[2ll * BCHW];
__device__ __align__(128) __half g_Fh[2ll * BCHW];

__device__ __forceinline__ void mma16816(float c[4],
    uint32_t a0, uint32_t a1, uint32_t a2, uint32_t a3,
    uint32_t b0, uint32_t b1) {
  asm volatile(
    "mma.sync.aligned.m16n8k16.row.col.f32.f16.f16.f32 "
    "{%0,%1,%2,%3}, {%4,%5,%6,%7}, {%8,%9}, {%0,%1,%2,%3};\n"
    : "+f"(c[0]), "+f"(c[1]), "+f"(c[2]), "+f"(c[3])
    : "r"(a0), "r"(a1), "r"(a2), "r"(a3), "r"(b0), "r"(b1));
}
__device__ __forceinline__ uint32_t pack2(float x, float y) {
  __half2 h = __floats2half2_rn(x, y);
  return *reinterpret_cast<uint32_t*>(&h);
}

__device__ __forceinline__ void gemm128(const __half* A, const __half* W,
                                        float acc[2][8][4],
                                        int wm, int wn, int g, int tg) {
#pragma unroll
  for (int kk = 0; kk < 8; kk++) {
    int cb = kk * 16 + 2 * tg;
    uint32_t af[2][4], bf[8][2];
#pragma unroll
    for (int mt = 0; mt < 2; mt++) {
      int r = wm * 32 + mt * 16;
      af[mt][0] = *(const uint32_t*)&A[(r + g) * 136 + cb];
      af[mt][1] = *(const uint32_t*)&A[(r + g + 8) * 136 + cb];
      af[mt][2] = *(const uint32_t*)&A[(r + g) * 136 + cb + 8];
      af[mt][3] = *(const uint32_t*)&A[(r + g + 8) * 136 + cb + 8];
    }
#pragma unroll
    for (int nt = 0; nt < 8; nt++) {
      int o = wn * 64 + nt * 8 + g;
      bf[nt][0] = *(const uint32_t*)&W[o * 136 + cb];
      bf[nt][1] = *(const uint32_t*)&W[o * 136 + cb + 8];
    }
#pragma unroll
    for (int mt = 0; mt < 2; mt++)
#pragma unroll
      for (int nt = 0; nt < 8; nt++)
        mma16816(acc[mt][nt], af[mt][0], af[mt][1], af[mt][2], af[mt][3],
                 bf[nt][0], bf[nt][1]);
  }
}
__device__ __forceinline__ void zacc(float acc[2][8][4]) {
#pragma unroll
  for (int mt = 0; mt < 2; mt++)
#pragma unroll
    for (int nt = 0; nt < 8; nt++)
#pragma unroll
      for (int q = 0; q < 4; q++) acc[mt][nt][q] = 0.f;
}

// ===========================================================================
struct PrepArgs { const float* w[11]; };
__global__ __launch_bounds__(256) void k0_prep(PrepArgs a) {
  int i = blockIdx.x * 256 + threadIdx.x;
  if (i >= 229376) return;
  float v;
  if (i < 98304)       v = a.w[i / 16384][i & 16383];
  else if (i < 131072) { int t = i - 98304;  v = a.w[6 + t / 16384][t & 16383]; }
  else                 { int t = i - 131072; v = a.w[8 + t / 32768][t & 32767]; }
  g_wh[i] = __float2half(v);
}

// ===========================================================================
struct K1Args { const float* x[2]; const float* bi[6]; };

__global__ __launch_bounds__(256, 2) void k1_qkv(K1Args a) {
  extern __shared__ char sm[];
  __half* Xs = (__half*)sm;
  __half* Ws = Xs + 128 * 136;

  int tile = blockIdx.x, z = blockIdx.y;
  int p0 = tile * 128;
  int b = p0 >> 16;
  int hw0 = p0 & 65535;
  int y = hw0 >> 8, x0 = hw0 & 255;
  int tid = threadIdx.x;
  const float* Xb = a.x[z] + (size_t)b * CHN * HWSZ + hw0;

  for (int j = tid; j < 64 * 128; j += 256) {
    int px = j & 127, cp = j >> 7;
    float v0 = Xb[(size_t)(2 * cp) * HWSZ + px];
    float v1 = Xb[(size_t)(2 * cp + 1) * HWSZ + px];
    *(uint32_t*)&Xs[px * 136 + 2 * cp] = pack2(v0, v1);
  }
  __syncthreads();

  {
    __half* fo = g_Fh + (size_t)z * BCHW + ((size_t)b * HWSZ + hw0) * 128;
    for (int j = tid; j < 2048; j += 256) {
      int px = j >> 4, c8 = (j & 15) * 8;
      *(uint4*)&fo[(size_t)px * 128 + c8] = *(const uint4*)&Xs[px * 136 + c8];
    }
  }

  int warp = tid >> 5, lane = tid & 31;
  int g = lane >> 2, tg = lane & 3;
  int wm = warp >> 1, wn = warp & 1;

  for (int p3 = 0; p3 < 3; p3++) {
    int wi = z * 3 + p3;
    __syncthreads();
    const __half* Wg = g_wh + wi * 16384;
    for (int j = tid; j < 2048; j += 256) {
      int o = j >> 4, c8 = (j & 15) * 8;
      *(uint4*)&Ws[o * 136 + c8] = *(const uint4*)&Wg[o * 128 + c8];
    }
    __syncthreads();

    float acc[2][8][4];
    zacc(acc);
    gemm128(Xs, Ws, acc, wm, wn, g, tg);
    __syncthreads();

    const float* Bv = a.bi[wi];
    float qs_ = (p3 == 0) ? 0.1767766952966369f : 1.0f;

    if (p3 < 2) {
#pragma unroll
      for (int mt = 0; mt < 2; mt++) {
        int px = wm * 32 + mt * 16 + g;
#pragma unroll
        for (int nt = 0; nt < 8; nt++) {
          int o = wn * 64 + nt * 8 + 2 * tg;
          *(uint32_t*)&Ws[px * 136 + o] =
              pack2((acc[mt][nt][0] + Bv[o]) * qs_, (acc[mt][nt][1] + Bv[o + 1]) * qs_);
          *(uint32_t*)&Ws[(px + 8) * 136 + o] =
              pack2((acc[mt][nt][2] + Bv[o]) * qs_, (acc[mt][nt][3] + Bv[o + 1]) * qs_);
        }
      }
      __syncthreads();
      __half* outp = g_qkT + (size_t)(z * 2 + p3) * BCHW;
      for (int j = tid; j < 2048; j += 256) {
        int px = j >> 4, c8 = (j & 15) * 8;
        int x = x0 + px;
        int win = b * 1024 + (y >> 3) * 32 + (x >> 3);
        int tok = (y & 7) * 8 + (x & 7);
        *(uint4*)&outp[((size_t)win * 64 + tok) * 128 + c8] =
            *(const uint4*)&Ws[px * 136 + c8];
      }
    } else {
#pragma unroll
      for (int mt = 0; mt < 2; mt++) {
        int px = wm * 32 + mt * 16 + g;
#pragma unroll
        for (int nt = 0; nt < 8; nt++) {
          int o = wn * 64 + nt * 8 + 2 * tg;
          Ws[o * 136 + px] = __float2half(acc[mt][nt][0] + Bv[o]);
          Ws[(o + 1) * 136 + px] = __float2half(acc[mt][nt][1] + Bv[o + 1]);
          Ws[o * 136 + px + 8] = __float2half(acc[mt][nt][2] + Bv[o]);
          Ws[(o + 1) * 136 + px + 8] = __float2half(acc[mt][nt][3] + Bv[o + 1]);
        }
      }
      __syncthreads();
      __half* outp = g_vwin + (size_t)z * BCHW;
      for (int j = tid; j < 2048; j += 256) {
        int ch = j >> 4, px8 = (j & 15) * 8;
        int x = x0 + px8;
        int win = b * 1024 + (y >> 3) * 32 + (x >> 3);
        int tokb = (y & 7) * 8;
        *(uint4*)&outp[((size_t)win * 128 + ch) * 64 + tokb] =
            *(const uint4*)&Ws[ch * 136 + px8];
      }
    }
  }
}

// ===========================================================================
__global__ __launch_bounds__(128, 3) void k2_attn() {
  extern __shared__ char sm[];
  __half* qs = (__half*)sm;
  __half* ks = qs + 64 * 136;
  __half* vs = ks + 64 * 136;
  __half* os = vs + 128 * 72;

  int win = blockIdx.x, d = blockIdx.y;
  int qslot = d == 0 ? 0 : 2;
  int kslot = d == 0 ? 3 : 1;
  int vz = d == 0 ? 1 : 0;
  int tid = threadIdx.x;

  const __half* Qg = g_qkT + ((size_t)qslot * NWIN + win) * TOK * CHN;
  const __half* Kg = g_qkT + ((size_t)kslot * NWIN + win) * TOK * CHN;
  const __half* Vg = g_vwin + (size_t)vz * BCHW + (size_t)win * CHN * TOK;

  for (int j = tid; j < 1024; j += 128) {
    int tok = j >> 4, c8 = (j & 15) * 8;
    *(uint4*)&qs[tok * 136 + c8] = *(const uint4*)&Qg[tok * 128 + c8];
    *(uint4*)&ks[tok * 136 + c8] = *(const uint4*)&Kg[tok * 128 + c8];
  }
  for (int j = tid; j < 1024; j += 128) {
    int ch = j >> 3, t8 = (j & 7) * 8;
    *(uint4*)&vs[ch * 72 + t8] = *(const uint4*)&Vg[ch * 64 + t8];
  }
  __syncthreads();

  int h = tid >> 5, lane = tid & 31;
  int g = lane >> 2, tg = lane & 3;

  for (int cq = 0; cq < 4; cq++) {
    int qr = cq * 16;
    float sc[8][4];
#pragma unroll
    for (int nt = 0; nt < 8; nt++)
#pragma unroll
      for (int q = 0; q < 4; q++) sc[nt][q] = 0.f;

#pragma unroll
    for (int kk = 0; kk < 2; kk++) {
      int cb = h * 32 + kk * 16 + 2 * tg;
      uint32_t a0 = *(const uint32_t*)&qs[(qr + g) * 136 + cb];
      uint32_t a1 = *(const uint32_t*)&qs[(qr + g + 8) * 136 + cb];
      uint32_t a2 = *(const uint32_t*)&qs[(qr + g) * 136 + cb + 8];
      uint32_t a3 = *(const uint32_t*)&qs[(qr + g + 8) * 136 + cb + 8];
#pragma unroll
      for (int nt = 0; nt < 8; nt++) {
        uint32_t b0 = *(const uint32_t*)&ks[(nt * 8 + g) * 136 + cb];
        uint32_t b1 = *(const uint32_t*)&ks[(nt * 8 + g) * 136 + cb + 8];
        mma16816(sc[nt], a0, a1, a2, a3, b0, b1);
      }
    }

    float m0 = -1e30f, m1 = -1e30f;
#pragma unroll
    for (int nt = 0; nt < 8; nt++) {
      m0 = fmaxf(m0, fmaxf(sc[nt][0], sc[nt][1]));
      m1 = fmaxf(m1, fmaxf(sc[nt][2], sc[nt][3]));
    }
#pragma unroll
    for (int o = 1; o < 4; o <<= 1) {
      m0 = fmaxf(m0, __shfl_xor_sync(0xffffffffu, m0, o));
      m1 = fmaxf(m1, __shfl_xor_sync(0xffffffffu, m1, o));
    }
    float l0 = 0.f, l1 = 0.f;
#pragma unroll
    for (int nt = 0; nt < 8; nt++) {
      sc[nt][0] = __expf(sc[nt][0] - m0);
      sc[nt][1] = __expf(sc[nt][1] - m0);
      sc[nt][2] = __expf(sc[nt][2] - m1);
      sc[nt][3] = __expf(sc[nt][3] - m1);
      l0 += sc[nt][0] + sc[nt][1];
      l1 += sc[nt][2] + sc[nt][3];
    }
#pragma unroll
    for (int o = 1; o < 4; o <<= 1) {
      l0 += __shfl_xor_sync(0xffffffffu, l0, o);
      l1 += __shfl_xor_sync(0xffffffffu, l1, o);
    }
    float r0 = 1.f / l0, r1 = 1.f / l1;

    float oacc[4][4];
#pragma unroll
    for (int nv = 0; nv < 4; nv++)
#pragma unroll
      for (int q = 0; q < 4; q++) oacc[nv][q] = 0.f;
#pragma unroll
    for (int kt = 0; kt < 4; kt++) {
      uint32_t a0 = pack2(sc[2 * kt][0] * r0, sc[2 * kt][1] * r0);
      uint32_t a1 = pack2(sc[2 * kt][2] * r1, sc[2 * kt][3] * r1);
      uint32_t a2 = pack2(sc[2 * kt + 1][0] * r0, sc[2 * kt + 1][1] * r0);
      uint32_t a3 = pack2(sc[2 * kt + 1][2] * r1, sc[2 * kt + 1][3] * r1);
#pragma unroll
      for (int nv = 0; nv < 4; nv++) {
        int ch = h * 32 + nv * 8 + g;
        uint32_t b0 = *(const uint32_t*)&vs[ch * 72 + kt * 16 + 2 * tg];
        uint32_t b1 = *(const uint32_t*)&vs[ch * 72 + kt * 16 + 2 * tg + 8];
        mma16816(oacc[nv], a0, a1, a2, a3, b0, b1);
      }
    }
#pragma unroll
    for (int nv = 0; nv < 4; nv++) {
      int cc = h * 32 + nv * 8 + 2 * tg;
      *(uint32_t*)&os[(qr + g) * 136 + cc] = pack2(oacc[nv][0], oacc[nv][1]);
      *(uint32_t*)&os[(qr + g + 8) * 136 + cc] = pack2(oacc[nv][2], oacc[nv][3]);
    }
  }
  __syncthreads();

  __half* outp = g_attn + ((size_t)d * NWIN + win) * TOK * CHN;
  for (int j = tid; j < 1024; j += 128) {
    int tok = j >> 4, c8 = (j & 15) * 8;
    *(uint4*)&outp[tok * 128 + c8] = *(const uint4*)&os[tok * 136 + c8];
  }
}

// ===========================================================================
struct MegaArgs {
  const float *pb0, *pb1, *gob, *gsb, *fb;
  const float *gamma, *beta, *mean, *var;
  float* out;
};

__global__ __launch_bounds__(256) void k3_mega(MegaArgs a) {
  extern __shared__ char sm[];
  __half* b0 = (__half*)sm;
  __half* b1 = b0 + 128 * 136;
  __half* b2 = b1 + 128 * 136;
  __half* b3 = b2 + 128 * 136;

  int wp = blockIdx.x;
  int tid = threadIdx.x;
  int warp = tid >> 5, lane = tid & 31;
  int g = lane >> 2, tg = lane & 3;
  int wm = warp >> 1, wn = warp & 1;

  {
    const __half* A0 = g_attn + ((size_t)0 * NWIN + (size_t)wp * 2) * TOK * CHN;
    const __half* A1 = g_attn + ((size_t)1 * NWIN + (size_t)wp * 2) * TOK * CHN;
    for (int j = tid; j < 2048; j += 256) {
      int r = j >> 4, c8 = (j & 15) * 8;
      *(uint4*)&b0[r * 136 + c8] = *(const uint4*)&A0[r * 128 + c8];
      *(uint4*)&b1[r * 136 + c8] = *(const uint4*)&A1[r * 128 + c8];
      *(uint4*)&b2[r * 136 + c8] = *(const uint4*)&g_wh[98304 + r * 128 + c8];
    }
  }
  __syncthreads();

  float acc[2][8][4];

  // proj o2s
  zacc(acc);
  gemm128(b0, b2, acc, wm, wn, g, tg);
  __syncthreads();
#pragma unroll
  for (int mt = 0; mt < 2; mt++) {
    int r = wm * 32 + mt * 16 + g;
#pragma unroll
    for (int nt = 0; nt < 8; nt++) {
      int o = wn * 64 + nt * 8 + 2 * tg;
      *(uint32_t*)&b3[r * 136 + o] =
          pack2(acc[mt][nt][0] + a.pb0[o], acc[mt][nt][1] + a.pb0[o + 1]);
      *(uint32_t*)&b3[(r + 8) * 136 + o] =
          pack2(acc[mt][nt][2] + a.pb0[o], acc[mt][nt][3] + a.pb0[o + 1]);
    }
  }
  for (int j = tid; j < 2048; j += 256) {
    int r = j >> 4, c8 = (j & 15) * 8;
    *(uint4*)&b2[r * 136 + c8] = *(const uint4*)&g_wh[114688 + r * 128 + c8];
  }
  __syncthreads();

  // proj s2o
  zacc(acc);
  gemm128(b1, b2, acc, wm, wn, g, tg);
  __syncthreads();
#pragma unroll
  for (int mt = 0; mt < 2; mt++) {
    int r = wm * 32 + mt * 16 + g;
#pragma unroll
    for (int nt = 0; nt < 8; nt++) {
      int o = wn * 64 + nt * 8 + 2 * tg;
      *(uint32_t*)&b1[r * 136 + o] =
          pack2(acc[mt][nt][0] + a.pb1[o], acc[mt][nt][1] + a.pb1[o + 1]);
      *(uint32_t*)&b1[(r + 8) * 136 + o] =
          pack2(acc[mt][nt][2] + a.pb1[o], acc[mt][nt][3] + a.pb1[o + 1]);
    }
  }
  for (int j = tid; j < 2048; j += 256) {
    int r = j >> 4, c8 = (j & 15) * 8;
    int win = wp * 2 + (r >> 6);
    int t6 = r & 63;
    int bb = win >> 10;
    int hw = ((win >> 5) & 31) * 2048 + (win & 31) * 8 + (t6 >> 3) * 256 + (t6 & 7);
    *(uint4*)&b0[r * 136 + c8] =
        *(const uint4*)&g_Fh[((size_t)bb * HWSZ + hw) * 128 + c8];
    *(uint4*)&b2[r * 136 + c8] = *(const uint4*)&g_wh[131072 + r * 256 + c8];
  }
  __syncthreads();

  // gate_opt K=256: half0 (F_opt), half1 (att0p)
  zacc(acc);
  gemm128(b0, b2, acc, wm, wn, g, tg);
  __syncthreads();
  for (int j = tid; j < 2048; j += 256) {
    int r = j >> 4, c8 = (j & 15) * 8;
    *(uint4*)&b2[r * 136 + c8] = *(const uint4*)&g_wh[131072 + r * 256 + 128 + c8];
  }
  __syncthreads();
  gemm128(b3, b2, acc, wm, wn, g, tg);
  __syncthreads();

  // sigma_opt + residual (opt_new -> b0)
#pragma unroll
  for (int mt = 0; mt < 2; mt++) {
    int r = wm * 32 + mt * 16 + g;
    int win = wp * 2 + (r >> 6);
    int bb = win >> 10;
    int hwbase = ((win >> 5) & 31) * 2048 + (win & 31) * 8;
    int t6 = r & 63;
    int hw1 = hwbase + (t6 >> 3) * 256 + (t6 & 7);
    int t68 = (r + 8) & 63;
    int hw2 = hwbase + (t68 >> 3) * 256 + (t68 & 7);
    float* sig = a.out + BCHW + (size_t)bb * CHN * HWSZ;
#pragma unroll
    for (int nt = 0; nt < 8; nt++) {
      int o = wn * 64 + nt * 8 + 2 * tg;
      float s0 = 1.f / (1.f + __expf(-(acc[mt][nt][0] + a.gob[o])));
      float s1 = 1.f / (1.f + __expf(-(acc[mt][nt][1] + a.gob[o + 1])));
      float s2 = 1.f / (1.f + __expf(-(acc[mt][nt][2] + a.gob[o])));
      float s3 = 1.f / (1.f + __expf(-(acc[mt][nt][3] + a.gob[o + 1])));
      sig[(size_t)o * HWSZ + hw1] = s0;
      sig[(size_t)(o + 1) * HWSZ + hw1] = s1;
      sig[(size_t)o * HWSZ + hw2] = s2;
      sig[(size_t)(o + 1) * HWSZ + hw2] = s3;
      __half2 f0 = *(const __half2*)&b0[r * 136 + o];
      __half2 f1 = *(const __half2*)&b0[(r + 8) * 136 + o];
      __half2 a0 = *(const __half2*)&b3[r * 136 + o];
      __half2 a1 = *(const __half2*)&b3[(r + 8) * 136 + o];
      *(uint32_t*)&b0[r * 136 + o] =
          pack2(__half2float(f0.x) + s0 * __half2float(a0.x),
                __half2float(f0.y) + s1 * __half2float(a0.y));
      *(uint32_t*)&b0[(r + 8) * 136 + o] =
          pack2(__half2float(f1.x) + s2 * __half2float(a1.x),
                __half2float(f1.y) + s3 * __half2float(a1.y));
    }
  }
  __syncthreads();

  // load F_sar -> b3, gate_sar half0 -> b2
  for (int j = tid; j < 2048; j += 256) {
    int r = j >> 4, c8 = (j & 15) * 8;
    int win = wp * 2 + (r >> 6);
    int t6 = r & 63;
    int bb = win >> 10;
    int hw = ((win >> 5) & 31) * 2048 + (win & 31) * 8 + (t6 >> 3) * 256 + (t6 & 7);
    *(uint4*)&b3[r * 136 + c8] =
        *(const uint4*)&g_Fh[BCHW + ((size_t)bb * HWSZ + hw) * 128 + c8];
    *(uint4*)&b2[r * 136 + c8] = *(const uint4*)&g_wh[163840 + r * 256 + c8];
  }
  __syncthreads();

  // gate_sar K=256: half0 (F_sar), half1 (att1p)
  zacc(acc);
  gemm128(b3, b2, acc, wm, wn, g, tg);
  __syncthreads();
  for (int j = tid; j < 2048; j += 256) {
    int r = j >> 4, c8 = (j & 15) * 8;
    *(uint4*)&b2[r * 136 + c8] = *(const uint4*)&g_wh[163840 + r * 256 + 128 + c8];
  }
  __syncthreads();
  gemm128(b1, b2, acc, wm, wn, g, tg);
  __syncthreads();

  // sigma_sar + residual (sar_new -> b1)
#pragma unroll
  for (int mt = 0; mt < 2; mt++) {
    int r = wm * 32 + mt * 16 + g;
    int win = wp * 2 + (r >> 6);
    int bb = win >> 10;
    int hwbase = ((win >> 5) & 31) * 2048 + (win & 31) * 8;
    int t6 = r & 63;
    int hw1 = hwbase + (t6 >> 3) * 256 + (t6 & 7);
    int t68 = (r + 8) & 63;
    int hw2 = hwbase + (t68 >> 3) * 256 + (t68 & 7);
    float* sig = a.out + 2 * BCHW + (size_t)bb * CHN * HWSZ;
#pragma unroll
    for (int nt = 0; nt < 8; nt++) {
      int o = wn * 64 + nt * 8 + 2 * tg;
      float s0 = 1.f / (1.f + __expf(-(acc[mt][nt][0] + a.gsb[o])));
      float s1 = 1.f / (1.f + __expf(-(acc[mt][nt][1] + a.gsb[o + 1])));
      float s2 = 1.f / (1.f + __expf(-(acc[mt][nt][2] + a.gsb[o])));
      float s3 = 1.f / (1.f + __expf(-(acc[mt][nt][3] + a.gsb[o + 1])));
      sig[(size_t)o * HWSZ + hw1] = s0;
      sig[(size_t)(o + 1) * HWSZ + hw1] = s1;
      sig[(size_t)o * HWSZ + hw2] = s2;
      sig[(size_t)(o + 1) * HWSZ + hw2] = s3;
      __half2 f0 = *(const __half2*)&b3[r * 136 + o];
      __half2 f1 = *(const __half2*)&b3[(r + 8) * 136 + o];
      __half2 a0 = *(const __half2*)&b1[r * 136 + o];
      __half2 a1 = *(const __half2*)&b1[(r + 8) * 136 + o];
      *(uint32_t*)&b1[r * 136 + o] =
          pack2(__half2float(f0.x) + s0 * __half2float(a0.x),
                __half2float(f0.y) + s1 * __half2float(a0.y));
      *(uint32_t*)&b1[(r + 8) * 136 + o] =
          pack2(__half2float(f1.x) + s2 * __half2float(a1.x),
                __half2float(f1.y) + s3 * __half2float(a1.y));
    }
  }
  for (int j = tid; j < 2048; j += 256) {
    int r = j >> 4, c8 = (j & 15) * 8;
    *(uint4*)&b2[r * 136 + c8] = *(const uint4*)&g_wh[196608 + r * 256 + c8];
  }
  __syncthreads();

  // fuse K=256: half0 (opt_new), half1 (sar_new)
  zacc(acc);
  gemm128(b0, b2, acc, wm, wn, g, tg);
  __syncthreads();
  for (int j = tid; j < 2048; j += 256) {
    int r = j >> 4, c8 = (j & 15) * 8;
    *(uint4*)&b2[r * 136 + c8] = *(const uint4*)&g_wh[196608 + r * 256 + 128 + c8];
  }
  __syncthreads();
  gemm128(b1, b2, acc, wm, wn, g, tg);

  // epilogue: +fb, BN, SiLU -> out
#pragma unroll
  for (int mt = 0; mt < 2; mt++) {
    int r = wm * 32 + mt * 16 + g;
    int win = wp * 2 + (r >> 6);
    int bb = win >> 10;
    int hwbase = ((win >> 5) & 31) * 2048 + (win & 31) * 8;
    int t6 = r & 63;
    int hw1 = hwbase + (t6 >> 3) * 256 + (t6 & 7);
    int t68 = (r + 8) & 63;
    int hw2 = hwbase + (t68 >> 3) * 256 + (t68 & 7);
    float* outp = a.out + (size_t)bb * CHN * HWSZ;
#pragma unroll
    for (int nt = 0; nt < 8; nt++) {
      int o = wn * 64 + nt * 8 + 2 * tg;
      float inv0 = a.gamma[o] * rsqrtf(a.var[o] + 1e-5f);
      float inv1 = a.gamma[o + 1] * rsqrtf(a.var[o + 1] + 1e-5f);
      float sh0 = a.beta[o] - a.mean[o] * inv0;
      float sh1 = a.beta[o + 1] - a.mean[o + 1] * inv1;
      float v0 = (acc[mt][nt][0] + a.fb[o]) * inv0 + sh0;
      float v1 = (acc[mt][nt][1] + a.fb[o + 1]) * inv1 + sh1;
      float v2 = (acc[mt][nt][2] + a.fb[o]) * inv0 + sh0;
      float v3 = (acc[mt][nt][3] + a.fb[o + 1]) * inv1 + sh1;
      outp[(size_t)o * HWSZ + hw1] = v0 / (1.f + __expf(-v0));
      outp[(size_t)(o + 1) * HWSZ + hw1] = v1 / (1.f + __expf(-v1));
      outp[(size_t)o * HWSZ + hw2] = v2 / (1.f + __expf(-v2));
      outp[(size_t)(o + 1) * HWSZ + hw2] = v3 / (1.f + __expf(-v3));
    }
  }
}

// ===========================================================================
extern "C" void kernel_launch(void* const* d_in, const int* in_sizes, int n_in,
                              void* d_out, int out_size) {
  const float* F_opt = (const float*)d_in[0];
  const float* F_sar = (const float*)d_in[1];

  cudaFuncSetAttribute(k1_qkv, cudaFuncAttributeMaxDynamicSharedMemorySize, 69632);
  cudaFuncSetAttribute(k2_attn, cudaFuncAttributeMaxDynamicSharedMemorySize, 70656);
  cudaFuncSetAttribute(k3_mega, cudaFuncAttributeMaxDynamicSharedMemorySize, 139264);

  PrepArgs pa;
  pa.w[0] = (const float*)d_in[2];
  pa.w[1] = (const float*)d_in[4];
  pa.w[2] = (const float*)d_in[6];
  pa.w[3] = (const float*)d_in[8];
  pa.w[4] = (const float*)d_in[10];
  pa.w[5] = (const float*)d_in[12];
  pa.w[6] = (const float*)d_in[14];
  pa.w[7] = (const float*)d_in[16];
  pa.w[8] = (const float*)d_in[18];
  pa.w[9] = (const float*)d_in[20];
  pa.w[10] = (const float*)d_in[22];
  k0_prep<<<896, 256>>>(pa);

  K1Args a1;
  a1.x[0] = F_opt; a1.x[1] = F_sar;
  a1.bi[0] = (const float*)d_in[3];
  a1.bi[1] = (const float*)d_in[5];
  a1.bi[2] = (const float*)d_in[7];
  a1.bi[3] = (const float*)d_in[9];
  a1.bi[4] = (const float*)d_in[11];
  a1.bi[5] = (const float*)d_in[13];
  k1_qkv<<<dim3(2048, 2), 256, 69632>>>(a1);

  k2_attn<<<dim3(4096, 2), 128, 70656>>>();

  MegaArgs ma;
  ma.pb0 = (const float*)d_in[15];
  ma.pb1 = (const float*)d_in[17];
  ma.gob = (const float*)d_in[19];
  ma.gsb = (const float*)d_in[21];
  ma.fb = (const float*)d_in[23];
  ma.gamma = (const float*)d_in[24];
  ma.beta = (const float*)d_in[25];
  ma.mean = (const float*)d_in[26];
  ma.var = (const float*)d_in[27];
  ma.out = (float*)d_out;
  k3_mega<<<2048, 256, 139264>>>(ma);
}